// round 12
// baseline (speedup 1.0000x reference)
#include <cuda_runtime.h>
#include <cuda_fp16.h>
#include <cstdint>

#define Gn 128
#define Sn 32
#define Nn 32
#define Dn 128
#define Ln 3
#define Hn 4
#define HDn 32
#define Tn (Gn*Sn*Nn)        // 131072
#define TOn (Gn*Nn)          // 4096
#define En 1048576
#define EOn 16384
#define NTASK 10
#define EPSn 1e-5f

// ---------------- device scratch (allocation-free) ----------------
__device__ __half g_xh[Tn*Dn];       // fp16 mirror of x
__device__ __half g_agg1h[Tn*Dn];    // fp16 aggregate (big graph)
__device__ __half g_c1h[Tn*Dn];      // fp16 conv1 output
__device__ float  g_sub[Gn*Sn*Dn];
__device__ __half g_subh[Gn*Sn*Dn];
__device__ float  g_q[Gn*Sn*Dn];
__device__ float  g_k[Gn*Sn*Dn];
__device__ float  g_attn[Gn*Sn*Sn];
__device__ __half g_xatth[TOn*Dn];
__device__ __half g_agg2h[TOn*Dn];
__device__ float  g_c2[TOn*Dn];
__device__ float  g_h2[TOn*Dn];
__device__ float  g_acc[512];
__device__ __half g_wh[6 * Ln * Dn * Dn];   // transposed half weights [which][l][n][k]
// combined CSR scratch
__device__ int g_degs[Tn + TOn];
__device__ int g_offs[Tn + 1 + TOn + 1];
__device__ int g_curs[Tn + TOn];
__device__ int g_srcs_all[En + EOn];

// ---------------- weight convert + transpose: wh[w][l][n][k] = W[w][l][k][n] ----------------
__global__ void wconv_kernel(const float* __restrict__ Wr1, const float* __restrict__ Wn1,
                             const float* __restrict__ Wr2, const float* __restrict__ Wn2,
                             const float* __restrict__ Wq,  const float* __restrict__ Wk,
                             __half* __restrict__ wh)
{
    int idx = blockIdx.x * blockDim.x + threadIdx.x;      // 0 .. Ln*Dn*Dn-1
    int which = blockIdx.y;
    const float* src = (which == 0) ? Wr1 : (which == 1) ? Wn1 : (which == 2) ? Wr2
                     : (which == 3) ? Wn2 : (which == 4) ? Wq : Wk;
    int l = idx / (Dn * Dn), rem = idx % (Dn * Dn);
    int k = rem / Dn, n = rem % Dn;
    wh[((size_t)which * Ln + l) * Dn * Dn + n * Dn + k] = __float2half_rn(src[idx]);
}

// ---------------- layer-0 x -> half mirror, also zeroes deg counters ----------------
__global__ void x2half_kernel(const float* __restrict__ x, __half* __restrict__ xh,
                              int* __restrict__ degs)
{
    int idx = blockIdx.x * blockDim.x + threadIdx.x;
    if (idx < Tn + TOn) degs[idx] = 0;
    if (idx < Tn * Dn / 2) {
        float2 v = __ldg(((const float2*)x) + idx);
        ((__half2*)xh)[idx] = __floats2half2_rn(v.x, v.y);
    }
}

// ---------------- CSR build ----------------
__global__ void hist_both(const int* __restrict__ dstBig, const int* __restrict__ dstSmall,
                          int* __restrict__ degs)
{
    int e = blockIdx.x * blockDim.x + threadIdx.x;
    if (e < En) {
        atomicAdd(&degs[__ldg(&dstBig[e])], 1);
    } else if (e < En + EOn) {
        atomicAdd(&degs[Tn + __ldg(&dstSmall[e - En])], 1);
    }
}

__global__ __launch_bounds__(1024)
void scan_both(const int* __restrict__ degs, int* __restrict__ offs, int* __restrict__ curs)
{
    __shared__ int part[1024];
    const int t = threadIdx.x;
    const int n = (blockIdx.x == 0) ? Tn : TOn;
    const int dbase = (blockIdx.x == 0) ? 0 : Tn;
    const int obase = (blockIdx.x == 0) ? 0 : (Tn + 1);
    const int chunk = n / 1024;
    const int base = t * chunk;
    int s = 0;
    for (int i = 0; i < chunk; i++) s += degs[dbase + base + i];
    part[t] = s;
    __syncthreads();
    for (int d = 1; d < 1024; d <<= 1) {
        int v = (t >= d) ? part[t - d] : 0;
        __syncthreads();
        part[t] += v;
        __syncthreads();
    }
    int run = (t > 0) ? part[t - 1] : 0;
    for (int i = 0; i < chunk; i++) {
        offs[obase + base + i] = run;
        curs[dbase + base + i] = run;
        run += degs[dbase + base + i];
    }
    if (t == 1023) offs[obase + n] = run;
}

__global__ void fill_both(const int* __restrict__ ei, const int* __restrict__ oei,
                          int* __restrict__ curs, int* __restrict__ srcs_all)
{
    int e = blockIdx.x * blockDim.x + threadIdx.x;
    if (e < En) {
        int d = __ldg(&ei[En + e]);
        int pos = atomicAdd(&curs[d], 1);
        srcs_all[pos] = __ldg(&ei[e]);
    } else if (e < En + EOn) {
        int eo = e - En;
        int d = __ldg(&oei[EOn + eo]);
        int pos = atomicAdd(&curs[Tn + d], 1);
        srcs_all[En + pos] = __ldg(&oei[eo]);
    }
}

// ---------------- CSR gather: half in, fp32 accum, half out, 4 edges in flight ----------------
// Block 0 zeroes accZero[0:512] if non-null.
__global__ void gather_half(const __half* __restrict__ xh, const int* __restrict__ off,
                            const int* __restrict__ srcs, __half* __restrict__ aggh,
                            int nNodes, float* __restrict__ accZero)
{
    if (accZero && blockIdx.x == 0) {
        accZero[threadIdx.x] = 0.f;
        accZero[threadIdx.x + 256] = 0.f;
    }
    int node = (blockIdx.x * blockDim.x + threadIdx.x) >> 5;
    int lane = threadIdx.x & 31;
    if (node >= nNodes) return;
    int e0 = __ldg(&off[node]);
    int e1 = __ldg(&off[node + 1]);
    float4 a0 = make_float4(0.f, 0.f, 0.f, 0.f);
    float4 a1 = make_float4(0.f, 0.f, 0.f, 0.f);
    float4 a2 = make_float4(0.f, 0.f, 0.f, 0.f);
    float4 a3 = make_float4(0.f, 0.f, 0.f, 0.f);
    int e = e0;
    for (; e + 3 < e1; e += 4) {
        int s0 = __ldg(&srcs[e]);
        int s1 = __ldg(&srcs[e + 1]);
        int s2 = __ldg(&srcs[e + 2]);
        int s3 = __ldg(&srcs[e + 3]);
        uint2 u0 = __ldg(((const uint2*)(xh + (size_t)s0 * Dn)) + lane);
        uint2 u1 = __ldg(((const uint2*)(xh + (size_t)s1 * Dn)) + lane);
        uint2 u2 = __ldg(((const uint2*)(xh + (size_t)s2 * Dn)) + lane);
        uint2 u3 = __ldg(((const uint2*)(xh + (size_t)s3 * Dn)) + lane);
        float2 p, q;
        p = __half22float2(*(__half2*)&u0.x); q = __half22float2(*(__half2*)&u0.y);
        a0.x += p.x; a0.y += p.y; a0.z += q.x; a0.w += q.y;
        p = __half22float2(*(__half2*)&u1.x); q = __half22float2(*(__half2*)&u1.y);
        a1.x += p.x; a1.y += p.y; a1.z += q.x; a1.w += q.y;
        p = __half22float2(*(__half2*)&u2.x); q = __half22float2(*(__half2*)&u2.y);
        a2.x += p.x; a2.y += p.y; a2.z += q.x; a2.w += q.y;
        p = __half22float2(*(__half2*)&u3.x); q = __half22float2(*(__half2*)&u3.y);
        a3.x += p.x; a3.y += p.y; a3.z += q.x; a3.w += q.y;
    }
    for (; e < e1; e++) {
        int s0 = __ldg(&srcs[e]);
        uint2 u0 = __ldg(((const uint2*)(xh + (size_t)s0 * Dn)) + lane);
        float2 p = __half22float2(*(__half2*)&u0.x);
        float2 q = __half22float2(*(__half2*)&u0.y);
        a0.x += p.x; a0.y += p.y; a0.z += q.x; a0.w += q.y;
    }
    a0.x += a1.x + a2.x + a3.x;
    a0.y += a1.y + a2.y + a3.y;
    a0.z += a1.z + a2.z + a3.z;
    a0.w += a1.w + a2.w + a3.w;
    uint2 o;
    *(__half2*)&o.x = __floats2half2_rn(a0.x, a0.y);
    *(__half2*)&o.y = __floats2half2_rn(a0.z, a0.w);
    ((uint2*)(aggh + (size_t)node * Dn))[lane] = o;
}

// ---------------- cp.async helpers ----------------
__device__ __forceinline__ void cpasync16(void* dst, const void* src)
{
    uint32_t d = (uint32_t)__cvta_generic_to_shared(dst);
    asm volatile("cp.async.cg.shared.global [%0], [%1], 16;" :: "r"(d), "l"(src));
}
__device__ __forceinline__ void cpasync_commit() { asm volatile("cp.async.commit_group;"); }
template<int N> __device__ __forceinline__ void cpasync_wait() { asm volatile("cp.async.wait_group %0;" :: "n"(N)); }

// ---------------- fp16 tensor-core GEMM: C = A1@W1 (+ A2@W2) + bias ----------------
// A row-major half [m][128]; W transposed half [n][128]. 128x128 tile, BK=16,
// 2-stage double buffer, 256 threads (8 warps 2x4), warp tile 64x32 via m16n8k16.
// fp32 accumulate + epilogue. If Chin != nullptr (and blockIdx.y==0), the output is
// written as fp16 to Chin INSTEAD of fp32 Cin. blockIdx.y==1 selects (W1b, biasb, Cb).
#define ASTRH 24                 // halves per row (16 + 8 pad) -> 12 uints, conflict-free
#define A_STH (128 * ASTRH)
#define B_STH (128 * ASTRH)
__global__ __launch_bounds__(256)
void conv_gemm_f16(const __half* __restrict__ A1, const __half* __restrict__ A2,
                   const __half* __restrict__ W1in, const __half* __restrict__ W2,
                   const float* __restrict__ biasin, float* __restrict__ Cin,
                   float* __restrict__ statAcc, __half* __restrict__ Chin,
                   const __half* __restrict__ W1b, const float* __restrict__ biasb,
                   float* __restrict__ Cb)
{
    __shared__ __half As[2 * A_STH];
    __shared__ __half Bs[2 * B_STH];

    const __half* W1 = (blockIdx.y == 0) ? W1in : W1b;
    const float* bias = (blockIdx.y == 0) ? biasin : biasb;
    float* C = (blockIdx.y == 0) ? Cin : Cb;
    __half* Ch = (blockIdx.y == 0) ? Chin : nullptr;

    const int tid = threadIdx.x;
    const int wid = tid >> 5, lane = tid & 31;
    const int wm = wid >> 2, wn = wid & 3;
    const int group = lane >> 2, tig = lane & 3;
    const int row0 = blockIdx.x * 128;
    const int nst = (A2 != nullptr) ? 16 : 8;

    float acc[4][4][4];
#pragma unroll
    for (int i = 0; i < 4; i++)
#pragma unroll
        for (int j = 0; j < 4; j++)
#pragma unroll
            for (int r = 0; r < 4; r++) acc[i][j][r] = 0.f;

    auto load_stage = [&](int kt) {
        const __half* A = (kt >= 8) ? A2 : A1;
        const __half* W = (kt >= 8) ? W2 : W1;
        const int kg = (kt & 7) * 16;
        __half* as = As + (kt & 1) * A_STH;
        __half* bs = Bs + (kt & 1) * B_STH;
        {   // A tile: 128 rows x 16 halves
            int row = tid >> 1, koff = (tid & 1) * 8;
            cpasync16(as + row * ASTRH + koff,
                      A + (size_t)(row0 + row) * Dn + kg + koff);
        }
        {   // B tile: 128 n x 16 halves
            int n = tid >> 1, koff = (tid & 1) * 8;
            cpasync16(bs + n * ASTRH + koff,
                      W + (size_t)n * Dn + kg + koff);
        }
        cpasync_commit();
    };

    load_stage(0);
    for (int s = 0; s < nst; s++) {
        if (s + 1 < nst) { load_stage(s + 1); cpasync_wait<1>(); }
        else             { cpasync_wait<0>(); }
        __syncthreads();

        const uint32_t* sa = (const uint32_t*)(As + (s & 1) * A_STH);
        const uint32_t* sb = (const uint32_t*)(Bs + (s & 1) * B_STH);
        uint32_t ua[4][4], ub[4][2];
#pragma unroll
        for (int i = 0; i < 4; i++) {
            int r = wm * 64 + i * 16 + group;
            ua[i][0] = sa[r * 12 + tig];
            ua[i][1] = sa[(r + 8) * 12 + tig];
            ua[i][2] = sa[r * 12 + tig + 4];
            ua[i][3] = sa[(r + 8) * 12 + tig + 4];
        }
#pragma unroll
        for (int j = 0; j < 4; j++) {
            int n = wn * 32 + j * 8 + group;
            ub[j][0] = sb[n * 12 + tig];
            ub[j][1] = sb[n * 12 + tig + 4];
        }
#pragma unroll
        for (int i = 0; i < 4; i++)
#pragma unroll
            for (int j = 0; j < 4; j++) {
                asm volatile(
                    "mma.sync.aligned.m16n8k16.row.col.f32.f16.f16.f32 "
                    "{%0,%1,%2,%3}, {%4,%5,%6,%7}, {%8,%9}, {%0,%1,%2,%3};"
                    : "+f"(acc[i][j][0]), "+f"(acc[i][j][1]),
                      "+f"(acc[i][j][2]), "+f"(acc[i][j][3])
                    : "r"(ua[i][0]), "r"(ua[i][1]), "r"(ua[i][2]), "r"(ua[i][3]),
                      "r"(ub[j][0]), "r"(ub[j][1]));
            }
        __syncthreads();
    }

#pragma unroll
    for (int j = 0; j < 4; j++) {
        const int n = wn * 32 + j * 8 + tig * 2;
        const float bv0 = __ldg(&bias[n]);
        const float bv1 = __ldg(&bias[n + 1]);
        float s0 = 0.f, s1 = 0.f, q0 = 0.f, q1 = 0.f;
#pragma unroll
        for (int i = 0; i < 4; i++) {
            const int row = row0 + wm * 64 + i * 16 + group;
            float v0 = acc[i][j][0] + bv0;
            float v1 = acc[i][j][1] + bv1;
            float v2 = acc[i][j][2] + bv0;
            float v3 = acc[i][j][3] + bv1;
            if (Ch) {
                *(__half2*)(Ch + (size_t)row * Dn + n)       = __floats2half2_rn(v0, v1);
                *(__half2*)(Ch + (size_t)(row + 8) * Dn + n) = __floats2half2_rn(v2, v3);
            } else {
                *(float2*)(C + (size_t)row * Dn + n)       = make_float2(v0, v1);
                *(float2*)(C + (size_t)(row + 8) * Dn + n) = make_float2(v2, v3);
            }
            s0 += v0 + v2;  q0 += v0 * v0 + v2 * v2;
            s1 += v1 + v3;  q1 += v1 * v1 + v3 * v3;
        }
        if (statAcc) {
#pragma unroll
            for (int off = 4; off <= 16; off <<= 1) {
                s0 += __shfl_down_sync(0xffffffffu, s0, off);
                s1 += __shfl_down_sync(0xffffffffu, s1, off);
                q0 += __shfl_down_sync(0xffffffffu, q0, off);
                q1 += __shfl_down_sync(0xffffffffu, q1, off);
            }
            if (group == 0) {
                atomicAdd(&statAcc[n], s0);
                atomicAdd(&statAcc[Dn + n], q0);
                atomicAdd(&statAcc[n + 1], s1);
                atomicAdd(&statAcc[Dn + n + 1], q1);
            }
        }
    }
}

// ---------------- BN2: prep folded into apply ----------------
__global__ void bn_apply2(const float* __restrict__ c, const float* __restrict__ acc,
                          const float* __restrict__ gamma, const float* __restrict__ beta,
                          float* __restrict__ h)
{
    int idx = blockIdx.x * blockDim.x + threadIdx.x;
    if (idx >= TOn * Dn) return;
    int d = idx & (Dn - 1);
    float mu = acc[d] * (1.f / TOn);
    float var = acc[Dn + d] * (1.f / TOn) - mu * mu;
    float sc = gamma[d] * rsqrtf(var + EPSn);
    float sh = beta[d] - mu * sc;
    h[idx] = sc * c[idx] + sh;
}

// ---------------- sub = mean over N (layer 0 only), fp32 + half ----------------
__global__ void submean_kernel(const float* __restrict__ x, float* __restrict__ sub,
                               __half* __restrict__ subh)
{
    int b = blockIdx.x;
    int d = threadIdx.x;
    const float* xp = x + (size_t)b * Nn * Dn;
    float s = 0.f;
#pragma unroll 8
    for (int n = 0; n < Nn; n++) s += xp[n * Dn + d];
    float m = s * (1.f / Nn);
    sub[(size_t)b * Dn + d] = m;
    subh[(size_t)b * Dn + d] = __float2half_rn(m);
}

// ---------------- attention: per-graph 32x32, head-averaged softmax ----------------
__global__ void attn_kernel(const float* __restrict__ q, const float* __restrict__ k,
                            float* __restrict__ attn)
{
    int g = blockIdx.x;
    int tid = threadIdx.x;              // 128
    __shared__ float qs[Dn * 33];
    __shared__ float ks[Sn * Dn];
    __shared__ float at[Sn * Sn];
    const float* qg = q + (size_t)g * Sn * Dn;
    const float* kg = k + (size_t)g * Sn * Dn;
    for (int i = tid; i < Sn * Dn; i += 128) {
        int qi = i >> 7, c = i & 127;
        qs[c * 33 + qi] = qg[i];
        ks[i] = kg[i];
    }
    for (int i = tid; i < Sn * Sn; i += 128) at[i] = 0.f;
    __syncthreads();

    int h = tid >> 5;
    int qi = tid & 31;
    const float scale = 0.17677669529663687f;  // 1/sqrt(32)
    float sc[Sn];
    float mx = -1e30f;
#pragma unroll
    for (int j = 0; j < Sn; j++) {
        float dsum = 0.f;
#pragma unroll
        for (int hd = 0; hd < HDn; hd++)
            dsum += qs[(h * HDn + hd) * 33 + qi] * ks[j * Dn + h * HDn + hd];
        sc[j] = dsum * scale;
        mx = fmaxf(mx, sc[j]);
    }
    float se = 0.f;
#pragma unroll
    for (int j = 0; j < Sn; j++) { sc[j] = expf(sc[j] - mx); se += sc[j]; }
    float inv = 0.25f / se;
#pragma unroll
    for (int j = 0; j < Sn; j++) atomicAdd(&at[qi * Sn + j], sc[j] * inv);
    __syncthreads();
    for (int i = tid; i < Sn * Sn; i += 128) attn[(size_t)g * Sn * Sn + i] = at[i];
}

// ---------------- x_atten[g,n,d] = sum_s attn[g,s,n]*xh[g,s,n,d] -> half ----------------
__global__ void xatten_kernel(const __half* __restrict__ xh, const float* __restrict__ attn,
                              __half* __restrict__ xatth)
{
    int b = blockIdx.x;                 // g*Nn + n
    int g = b >> 5, n = b & 31;
    int d = threadIdx.x;                // 128
    __shared__ float coef[Sn];
    if (d < Sn) coef[d] = attn[(size_t)g * Sn * Sn + d * Sn + n];
    __syncthreads();
    float acc = 0.f;
#pragma unroll 8
    for (int s = 0; s < Sn; s++)
        acc += coef[s] * __half2float(xh[(size_t)((g * Sn + s) * Nn + n) * Dn + d]);
    xatth[(size_t)b * Dn + d] = __float2half_rn(acc);
}

// ---------------- combine: relu(BN1(c1h)+h2) -> xh mirror + submean (no fp32 x) ----------------
__global__ void combine_fused(const __half* __restrict__ c1h, const float* __restrict__ acc,
                              const float* __restrict__ gamma, const float* __restrict__ beta,
                              const float* __restrict__ h2,
                              float* __restrict__ sub, __half* __restrict__ subh,
                              __half* __restrict__ xh)
{
    int b = blockIdx.x;          // g*Sn + s
    int g = b >> 5;
    int d = threadIdx.x;         // 128
    float mu = acc[d] * (1.f / Tn);
    float var = acc[Dn + d] * (1.f / Tn) - mu * mu;
    const float sc = gamma[d] * rsqrtf(var + EPSn);
    const float sh = beta[d] - mu * sc;
    const __half* c1p = c1h + (size_t)b * Nn * Dn;
    const float* h2p = h2 + (size_t)g * Nn * Dn;
    __half* xhp = xh ? (xh + (size_t)b * Nn * Dn) : nullptr;
    float s = 0.f;
#pragma unroll 4
    for (int n = 0; n < Nn; n++) {
        float v = fmaxf(sc * __half2float(c1p[n * Dn + d]) + sh + h2p[n * Dn + d], 0.f);
        if (xhp) xhp[n * Dn + d] = __float2half_rn(v);
        s += v;
    }
    float m = s * (1.f / Nn);
    sub[(size_t)b * Dn + d] = m;
    subh[(size_t)b * Dn + d] = __float2half_rn(m);
}

// ---------------- head: pool(sub) -> MLP -> logits, + heatmap copy ----------------
__global__ __launch_bounds__(256)
void head_kernel(const float* __restrict__ sub, const float* __restrict__ Wf1,
                 const float* __restrict__ bf1, const float* __restrict__ Wf2,
                 const float* __restrict__ bf2, const float* __restrict__ attn,
                 float* __restrict__ out)
{
    int g = blockIdx.x;
    int tid = threadIdx.x;  // 256
    __shared__ float hv[Dn];
    __shared__ float hid[2 * Dn];
    if (tid < Dn) {
        float s = 0.f;
#pragma unroll 8
        for (int i = 0; i < Sn; i++) s += sub[(size_t)(g * Sn + i) * Dn + tid];
        hv[tid] = s * (1.f / Sn);
    }
    __syncthreads();
    float a = bf1[tid];
#pragma unroll 8
    for (int k2 = 0; k2 < Dn; k2++) a += hv[k2] * Wf1[(size_t)k2 * 2 * Dn + tid];
    hid[tid] = fmaxf(a, 0.f);
    __syncthreads();
    if (tid < NTASK) {
        float o = bf2[tid];
        for (int k2 = 0; k2 < 2 * Dn; k2++) o += hid[k2] * Wf2[(size_t)k2 * NTASK + tid];
        out[(size_t)g * NTASK + tid] = o;
    }
    if (g == Gn - 1) {
        for (int i = tid; i < Sn * Sn; i += 256)
            out[Gn * NTASK + i] = attn[(size_t)(Gn - 1) * Sn * Sn + i];
    }
}

// ---------------- host orchestration ----------------
extern "C" void kernel_launch(void* const* d_in, const int* in_sizes, int n_in,
                              void* d_out, int out_size)
{
    const float* x_in = (const float*)d_in[0];
    const int*   ei   = (const int*)d_in[1];
    const int*   oei  = (const int*)d_in[2];
    const float* Wr1 = (const float*)d_in[3];
    const float* Wn1 = (const float*)d_in[4];
    const float* b1  = (const float*)d_in[5];
    const float* g1  = (const float*)d_in[6];
    const float* be1 = (const float*)d_in[7];
    const float* Wr2 = (const float*)d_in[8];
    const float* Wn2 = (const float*)d_in[9];
    const float* b2  = (const float*)d_in[10];
    const float* g2  = (const float*)d_in[11];
    const float* be2 = (const float*)d_in[12];
    const float* Wq  = (const float*)d_in[13];
    const float* bq  = (const float*)d_in[14];
    const float* Wk  = (const float*)d_in[15];
    const float* bk  = (const float*)d_in[16];
    const float* Wf1 = (const float*)d_in[17];
    const float* bf1 = (const float*)d_in[18];
    const float* Wf2 = (const float*)d_in[19];
    const float* bf2 = (const float*)d_in[20];
    float* out = (float*)d_out;

    float *psub, *pq, *pk, *pattn, *pc2, *ph2, *pacc;
    __half *pxh, *pagg1h, *pc1h, *psubh, *pxatth, *pagg2h, *pwh;
    int *pdegs, *poffs, *pcurs, *psrcs;
    cudaGetSymbolAddress((void**)&pxh,    g_xh);
    cudaGetSymbolAddress((void**)&pagg1h, g_agg1h);
    cudaGetSymbolAddress((void**)&pc1h,   g_c1h);
    cudaGetSymbolAddress((void**)&psub,   g_sub);
    cudaGetSymbolAddress((void**)&psubh,  g_subh);
    cudaGetSymbolAddress((void**)&pq,     g_q);
    cudaGetSymbolAddress((void**)&pk,     g_k);
    cudaGetSymbolAddress((void**)&pattn,  g_attn);
    cudaGetSymbolAddress((void**)&pxatth, g_xatth);
    cudaGetSymbolAddress((void**)&pagg2h, g_agg2h);
    cudaGetSymbolAddress((void**)&pc2,    g_c2);
    cudaGetSymbolAddress((void**)&ph2,    g_h2);
    cudaGetSymbolAddress((void**)&pacc,   g_acc);
    cudaGetSymbolAddress((void**)&pwh,    g_wh);
    cudaGetSymbolAddress((void**)&pdegs,  g_degs);
    cudaGetSymbolAddress((void**)&poffs,  g_offs);
    cudaGetSymbolAddress((void**)&pcurs,  g_curs);
    cudaGetSymbolAddress((void**)&psrcs,  g_srcs_all);

    // ---- startup: weight convert, half mirror + deg zero, CSR build ----
    wconv_kernel<<<dim3(Ln * Dn * Dn / 256, 6), 256>>>(Wr1, Wn1, Wr2, Wn2, Wq, Wk, pwh);
    x2half_kernel<<<(Tn * Dn / 2) / 256, 256>>>(x_in, pxh, pdegs);
    hist_both<<<(En + EOn) / 256, 256>>>(ei + En, oei + EOn, pdegs);
    scan_both<<<2, 1024>>>(pdegs, poffs, pcurs);
    fill_both<<<(En + EOn) / 256, 256>>>(ei, oei, pcurs, psrcs);

    const int* poffBig = poffs;
    const int* poffSm  = poffs + Tn + 1;
    const int* psrcBig = psrcs;
    const int* psrcSm  = psrcs + En;
    const size_t WSZ = (size_t)Ln * Dn * Dn;

    for (int i = 0; i < Ln; i++) {
        const size_t wOff = (size_t)i * Dn * Dn;
        const size_t vOff = (size_t)i * Dn;
        const __half* Wr1h = pwh + 0 * WSZ + wOff;
        const __half* Wn1h = pwh + 1 * WSZ + wOff;
        const __half* Wr2h = pwh + 2 * WSZ + wOff;
        const __half* Wn2h = pwh + 3 * WSZ + wOff;
        const __half* Wqh  = pwh + 4 * WSZ + wOff;
        const __half* Wkh  = pwh + 5 * WSZ + wOff;

        // subgraph-level GraphConv (+ fused BN stats; gather zeroes the stat acc)
        gather_half<<<(Tn * 32) / 256, 256>>>(pxh, poffBig, psrcBig, pagg1h, Tn, pacc);
        conv_gemm_f16<<<Tn / 128, 256>>>(pxh, pagg1h, Wr1h, Wn1h, b1 + vOff, nullptr,
                                         pacc, pc1h, nullptr, nullptr, nullptr);

        // attention branch
        if (i == 0) submean_kernel<<<Gn * Sn, 128>>>(x_in, psub, psubh);
        conv_gemm_f16<<<dim3((Gn * Sn) / 128, 2), 256>>>(
            psubh, nullptr, Wqh, nullptr, bq + vOff, pq, nullptr, nullptr,
            Wkh, bk + vOff, pk);
        attn_kernel<<<Gn, 128>>>(pq, pk, pattn);
        xatten_kernel<<<Gn * Nn, 128>>>(pxh, pattn, pxatth);

        // original-graph GraphConv (+ fused BN stats)
        gather_half<<<(TOn * 32) / 256, 256>>>(pxatth, poffSm, psrcSm, pagg2h, TOn, nullptr);
        conv_gemm_f16<<<TOn / 128, 256>>>(pxatth, pagg2h, Wr2h, Wn2h, b2 + vOff, pc2,
                                          pacc + 256, nullptr, nullptr, nullptr, nullptr);
        bn_apply2<<<(TOn * Dn) / 256, 256>>>(pc2, pacc + 256, g2 + vOff, be2 + vOff, ph2);

        // relu(BN1(c1h) + h2 broadcast) -> next-layer xh mirror + submean (no fp32 x)
        combine_fused<<<Gn * Sn, 128>>>(pc1h, pacc, g1 + vOff, be1 + vOff, ph2,
                                        psub, psubh, (i < Ln - 1) ? pxh : nullptr);
    }

    head_kernel<<<Gn, 256>>>(psub, Wf1, bf1, Wf2, bf2, pattn, out);
}

// round 13
// speedup vs baseline: 1.5921x; 1.5921x over previous
#include <cuda_runtime.h>
#include <cuda_fp16.h>
#include <cstdint>

#define Gn 128
#define Sn 32
#define Nn 32
#define Dn 128
#define Ln 3
#define Hn 4
#define HDn 32
#define Tn (Gn*Sn*Nn)        // 131072
#define TOn (Gn*Nn)          // 4096
#define En 1048576
#define EOn 16384
#define NTASK 10
#define EPSn 1e-5f
#define NBLK_BIG (Tn / 1024)          // 128
#define NBLK_ALL (NBLK_BIG + TOn/1024) // 132

// ---------------- device scratch (allocation-free) ----------------
__device__ __half g_xh[Tn*Dn];       // fp16 mirror of x
__device__ __half g_agg1h[Tn*Dn];    // fp16 aggregate (big graph)
__device__ float  g_c1[Tn*Dn];
__device__ float  g_sub[Gn*Sn*Dn];
__device__ __half g_subh[Gn*Sn*Dn];
__device__ float  g_q[Gn*Sn*Dn];
__device__ float  g_k[Gn*Sn*Dn];
__device__ float  g_attn[Gn*Sn*Sn];
__device__ __half g_xatth[TOn*Dn];
__device__ __half g_agg2h[TOn*Dn];
__device__ float  g_c2[TOn*Dn];
__device__ float  g_h2[TOn*Dn];
__device__ float  g_acc[512];
__device__ __half g_wh[6 * Ln * Dn * Dn];   // transposed half weights [which][l][n][k]
// combined CSR scratch
__device__ int g_degs[Tn + TOn];
__device__ int g_offs[Tn + 1 + TOn + 1];
__device__ int g_curs[Tn + TOn];
__device__ int g_srcs_all[En + EOn];
__device__ int g_bsums[NBLK_ALL];

// ---------------- weight convert + transpose: wh[w][l][n][k] = W[w][l][k][n] ----------------
__global__ void wconv_kernel(const float* __restrict__ Wr1, const float* __restrict__ Wn1,
                             const float* __restrict__ Wr2, const float* __restrict__ Wn2,
                             const float* __restrict__ Wq,  const float* __restrict__ Wk,
                             __half* __restrict__ wh)
{
    int idx = blockIdx.x * blockDim.x + threadIdx.x;      // 0 .. Ln*Dn*Dn-1
    int which = blockIdx.y;
    const float* src = (which == 0) ? Wr1 : (which == 1) ? Wn1 : (which == 2) ? Wr2
                     : (which == 3) ? Wn2 : (which == 4) ? Wq : Wk;
    int l = idx / (Dn * Dn), rem = idx % (Dn * Dn);
    int k = rem / Dn, n = rem % Dn;
    wh[((size_t)which * Ln + l) * Dn * Dn + n * Dn + k] = __float2half_rn(src[idx]);
}

// ---------------- layer-0 x -> half mirror, also zeroes deg counters ----------------
__global__ void x2half_kernel(const float* __restrict__ x, __half* __restrict__ xh,
                              int* __restrict__ degs)
{
    int idx = blockIdx.x * blockDim.x + threadIdx.x;
    if (idx < Tn + TOn) degs[idx] = 0;
    if (idx < Tn * Dn / 2) {
        float2 v = __ldg(((const float2*)x) + idx);
        ((__half2*)xh)[idx] = __floats2half2_rn(v.x, v.y);
    }
}

// ---------------- CSR build ----------------
__global__ void hist_both(const int* __restrict__ dstBig, const int* __restrict__ dstSmall,
                          int* __restrict__ degs)
{
    int e = blockIdx.x * blockDim.x + threadIdx.x;
    if (e < En) {
        atomicAdd(&degs[__ldg(&dstBig[e])], 1);
    } else if (e < En + EOn) {
        atomicAdd(&degs[Tn + __ldg(&dstSmall[e - En])], 1);
    }
}

// ---- 3-phase parallel scan over degs (big graph blocks 0..127, small 128..131) ----
__global__ __launch_bounds__(1024)
void scanA(const int* __restrict__ degs, int* __restrict__ offs, int* __restrict__ bsums)
{
    __shared__ int sh[1024];
    int b = blockIdx.x, t = threadIdx.x;
    int dIdx = b * 1024 + t;
    int oIdx = (b < NBLK_BIG) ? dIdx : (dIdx + 1);   // small-graph offs shifted by +1 (after offs[Tn])
    int v = degs[dIdx];
    sh[t] = v;
    __syncthreads();
    for (int d = 1; d < 1024; d <<= 1) {
        int u = (t >= d) ? sh[t - d] : 0;
        __syncthreads();
        sh[t] += u;
        __syncthreads();
    }
    offs[oIdx] = sh[t] - v;          // local exclusive prefix
    if (t == 1023) bsums[b] = sh[t];
}

__global__ void scanB(int* __restrict__ bsums)
{
    __shared__ int sh[NBLK_ALL];
    int t = threadIdx.x;
    if (t < NBLK_ALL) sh[t] = bsums[t];
    __syncthreads();
    if (t == 0) {
        int run = 0;
        for (int i = 0; i < NBLK_BIG; i++) { int v = sh[i]; sh[i] = run; run += v; }
        run = 0;
        for (int i = NBLK_BIG; i < NBLK_ALL; i++) { int v = sh[i]; sh[i] = run; run += v; }
    }
    __syncthreads();
    if (t < NBLK_ALL) bsums[t] = sh[t];
}

__global__ __launch_bounds__(1024)
void scanC(int* __restrict__ offs, int* __restrict__ curs, const int* __restrict__ bsums)
{
    int b = blockIdx.x, t = threadIdx.x;
    int dIdx = b * 1024 + t;
    int oIdx = (b < NBLK_BIG) ? dIdx : (dIdx + 1);
    int v = offs[oIdx] + __ldg(&bsums[b]);
    offs[oIdx] = v;
    curs[dIdx] = v;
    if (b == 0 && t == 0) {
        offs[Tn] = En;                 // big-graph total
        offs[Tn + 1 + TOn] = EOn;      // small-graph total
    }
}

__global__ void fill_both(const int* __restrict__ ei, const int* __restrict__ oei,
                          int* __restrict__ curs, int* __restrict__ srcs_all)
{
    int e = blockIdx.x * blockDim.x + threadIdx.x;
    if (e < En) {
        int d = __ldg(&ei[En + e]);
        int pos = atomicAdd(&curs[d], 1);
        srcs_all[pos] = __ldg(&ei[e]);
    } else if (e < En + EOn) {
        int eo = e - En;
        int d = __ldg(&oei[EOn + eo]);
        int pos = atomicAdd(&curs[Tn + d], 1);
        srcs_all[En + pos] = __ldg(&oei[eo]);
    }
}

// ---------------- CSR gather: half in, fp32 accum, half out (R11-proven, unroll 2) ----------------
// Block 0 zeroes accZero[0:512] if non-null.
__global__ void gather_half(const __half* __restrict__ xh, const int* __restrict__ off,
                            const int* __restrict__ srcs, __half* __restrict__ aggh,
                            int nNodes, float* __restrict__ accZero)
{
    if (accZero && blockIdx.x == 0) {
        accZero[threadIdx.x] = 0.f;
        accZero[threadIdx.x + 256] = 0.f;
    }
    int node = (blockIdx.x * blockDim.x + threadIdx.x) >> 5;
    int lane = threadIdx.x & 31;
    if (node >= nNodes) return;
    int e0 = __ldg(&off[node]);
    int e1 = __ldg(&off[node + 1]);
    float4 a0 = make_float4(0.f, 0.f, 0.f, 0.f);
    float4 a1 = make_float4(0.f, 0.f, 0.f, 0.f);
    int e = e0;
    for (; e + 1 < e1; e += 2) {
        int sA = __ldg(&srcs[e]);
        int sB = __ldg(&srcs[e + 1]);
        uint2 ua = __ldg(((const uint2*)(xh + (size_t)sA * Dn)) + lane);
        uint2 ub = __ldg(((const uint2*)(xh + (size_t)sB * Dn)) + lane);
        float2 fa0 = __half22float2(*(__half2*)&ua.x);
        float2 fa1 = __half22float2(*(__half2*)&ua.y);
        float2 fb0 = __half22float2(*(__half2*)&ub.x);
        float2 fb1 = __half22float2(*(__half2*)&ub.y);
        a0.x += fa0.x; a0.y += fa0.y; a0.z += fa1.x; a0.w += fa1.y;
        a1.x += fb0.x; a1.y += fb0.y; a1.z += fb1.x; a1.w += fb1.y;
    }
    if (e < e1) {
        int sA = __ldg(&srcs[e]);
        uint2 ua = __ldg(((const uint2*)(xh + (size_t)sA * Dn)) + lane);
        float2 fa0 = __half22float2(*(__half2*)&ua.x);
        float2 fa1 = __half22float2(*(__half2*)&ua.y);
        a0.x += fa0.x; a0.y += fa0.y; a0.z += fa1.x; a0.w += fa1.y;
    }
    a0.x += a1.x; a0.y += a1.y; a0.z += a1.z; a0.w += a1.w;
    uint2 o;
    *(__half2*)&o.x = __floats2half2_rn(a0.x, a0.y);
    *(__half2*)&o.y = __floats2half2_rn(a0.z, a0.w);
    ((uint2*)(aggh + (size_t)node * Dn))[lane] = o;
}

// ---------------- cp.async helpers ----------------
__device__ __forceinline__ void cpasync16(void* dst, const void* src)
{
    uint32_t d = (uint32_t)__cvta_generic_to_shared(dst);
    asm volatile("cp.async.cg.shared.global [%0], [%1], 16;" :: "r"(d), "l"(src));
}
__device__ __forceinline__ void cpasync_commit() { asm volatile("cp.async.commit_group;"); }
template<int N> __device__ __forceinline__ void cpasync_wait() { asm volatile("cp.async.wait_group %0;" :: "n"(N)); }

// ---------------- fp16 tensor-core GEMM: C = A1@W1 (+ A2@W2) + bias (R11-proven) ----------------
#define ASTRH 24
#define A_STH (128 * ASTRH)
#define B_STH (128 * ASTRH)
__global__ __launch_bounds__(256)
void conv_gemm_f16(const __half* __restrict__ A1, const __half* __restrict__ A2,
                   const __half* __restrict__ W1in, const __half* __restrict__ W2,
                   const float* __restrict__ biasin, float* __restrict__ Cin,
                   float* __restrict__ statAcc,
                   const __half* __restrict__ W1b, const float* __restrict__ biasb,
                   float* __restrict__ Cb)
{
    __shared__ __half As[2 * A_STH];
    __shared__ __half Bs[2 * B_STH];

    const __half* W1 = (blockIdx.y == 0) ? W1in : W1b;
    const float* bias = (blockIdx.y == 0) ? biasin : biasb;
    float* C = (blockIdx.y == 0) ? Cin : Cb;

    const int tid = threadIdx.x;
    const int wid = tid >> 5, lane = tid & 31;
    const int wm = wid >> 2, wn = wid & 3;
    const int group = lane >> 2, tig = lane & 3;
    const int row0 = blockIdx.x * 128;
    const int nst = (A2 != nullptr) ? 16 : 8;

    float acc[4][4][4];
#pragma unroll
    for (int i = 0; i < 4; i++)
#pragma unroll
        for (int j = 0; j < 4; j++)
#pragma unroll
            for (int r = 0; r < 4; r++) acc[i][j][r] = 0.f;

    auto load_stage = [&](int kt) {
        const __half* A = (kt >= 8) ? A2 : A1;
        const __half* W = (kt >= 8) ? W2 : W1;
        const int kg = (kt & 7) * 16;
        __half* as = As + (kt & 1) * A_STH;
        __half* bs = Bs + (kt & 1) * B_STH;
        {
            int row = tid >> 1, koff = (tid & 1) * 8;
            cpasync16(as + row * ASTRH + koff,
                      A + (size_t)(row0 + row) * Dn + kg + koff);
        }
        {
            int n = tid >> 1, koff = (tid & 1) * 8;
            cpasync16(bs + n * ASTRH + koff,
                      W + (size_t)n * Dn + kg + koff);
        }
        cpasync_commit();
    };

    load_stage(0);
    for (int s = 0; s < nst; s++) {
        if (s + 1 < nst) { load_stage(s + 1); cpasync_wait<1>(); }
        else             { cpasync_wait<0>(); }
        __syncthreads();

        const uint32_t* sa = (const uint32_t*)(As + (s & 1) * A_STH);
        const uint32_t* sb = (const uint32_t*)(Bs + (s & 1) * B_STH);
        uint32_t ua[4][4], ub[4][2];
#pragma unroll
        for (int i = 0; i < 4; i++) {
            int r = wm * 64 + i * 16 + group;
            ua[i][0] = sa[r * 12 + tig];
            ua[i][1] = sa[(r + 8) * 12 + tig];
            ua[i][2] = sa[r * 12 + tig + 4];
            ua[i][3] = sa[(r + 8) * 12 + tig + 4];
        }
#pragma unroll
        for (int j = 0; j < 4; j++) {
            int n = wn * 32 + j * 8 + group;
            ub[j][0] = sb[n * 12 + tig];
            ub[j][1] = sb[n * 12 + tig + 4];
        }
#pragma unroll
        for (int i = 0; i < 4; i++)
#pragma unroll
            for (int j = 0; j < 4; j++) {
                asm volatile(
                    "mma.sync.aligned.m16n8k16.row.col.f32.f16.f16.f32 "
                    "{%0,%1,%2,%3}, {%4,%5,%6,%7}, {%8,%9}, {%0,%1,%2,%3};"
                    : "+f"(acc[i][j][0]), "+f"(acc[i][j][1]),
                      "+f"(acc[i][j][2]), "+f"(acc[i][j][3])
                    : "r"(ua[i][0]), "r"(ua[i][1]), "r"(ua[i][2]), "r"(ua[i][3]),
                      "r"(ub[j][0]), "r"(ub[j][1]));
            }
        __syncthreads();
    }

#pragma unroll
    for (int j = 0; j < 4; j++) {
        const int n = wn * 32 + j * 8 + tig * 2;
        const float bv0 = __ldg(&bias[n]);
        const float bv1 = __ldg(&bias[n + 1]);
        float s0 = 0.f, s1 = 0.f, q0 = 0.f, q1 = 0.f;
#pragma unroll
        for (int i = 0; i < 4; i++) {
            const int row = row0 + wm * 64 + i * 16 + group;
            float v0 = acc[i][j][0] + bv0;
            float v1 = acc[i][j][1] + bv1;
            float v2 = acc[i][j][2] + bv0;
            float v3 = acc[i][j][3] + bv1;
            *(float2*)(C + (size_t)row * Dn + n)       = make_float2(v0, v1);
            *(float2*)(C + (size_t)(row + 8) * Dn + n) = make_float2(v2, v3);
            s0 += v0 + v2;  q0 += v0 * v0 + v2 * v2;
            s1 += v1 + v3;  q1 += v1 * v1 + v3 * v3;
        }
        if (statAcc) {
#pragma unroll
            for (int off = 4; off <= 16; off <<= 1) {
                s0 += __shfl_down_sync(0xffffffffu, s0, off);
                s1 += __shfl_down_sync(0xffffffffu, s1, off);
                q0 += __shfl_down_sync(0xffffffffu, q0, off);
                q1 += __shfl_down_sync(0xffffffffu, q1, off);
            }
            if (group == 0) {
                atomicAdd(&statAcc[n], s0);
                atomicAdd(&statAcc[Dn + n], q0);
                atomicAdd(&statAcc[n + 1], s1);
                atomicAdd(&statAcc[Dn + n + 1], q1);
            }
        }
    }
}

// ---------------- BN2: prep folded into apply ----------------
__global__ void bn_apply2(const float* __restrict__ c, const float* __restrict__ acc,
                          const float* __restrict__ gamma, const float* __restrict__ beta,
                          float* __restrict__ h)
{
    int idx = blockIdx.x * blockDim.x + threadIdx.x;
    if (idx >= TOn * Dn) return;
    int d = idx & (Dn - 1);
    float mu = acc[d] * (1.f / TOn);
    float var = acc[Dn + d] * (1.f / TOn) - mu * mu;
    float sc = gamma[d] * rsqrtf(var + EPSn);
    float sh = beta[d] - mu * sc;
    h[idx] = sc * c[idx] + sh;
}

// ---------------- sub = mean over N (layer 0 only), fp32 + half ----------------
__global__ void submean_kernel(const float* __restrict__ x, float* __restrict__ sub,
                               __half* __restrict__ subh)
{
    int b = blockIdx.x;
    int d = threadIdx.x;
    const float* xp = x + (size_t)b * Nn * Dn;
    float s = 0.f;
#pragma unroll 8
    for (int n = 0; n < Nn; n++) s += xp[n * Dn + d];
    float m = s * (1.f / Nn);
    sub[(size_t)b * Dn + d] = m;
    subh[(size_t)b * Dn + d] = __float2half_rn(m);
}

// ---------------- attention: per-graph 32x32, head-averaged softmax ----------------
__global__ void attn_kernel(const float* __restrict__ q, const float* __restrict__ k,
                            float* __restrict__ attn)
{
    int g = blockIdx.x;
    int tid = threadIdx.x;              // 128
    __shared__ float qs[Dn * 33];
    __shared__ float ks[Sn * Dn];
    __shared__ float at[Sn * Sn];
    const float* qg = q + (size_t)g * Sn * Dn;
    const float* kg = k + (size_t)g * Sn * Dn;
    for (int i = tid; i < Sn * Dn; i += 128) {
        int qi = i >> 7, c = i & 127;
        qs[c * 33 + qi] = qg[i];
        ks[i] = kg[i];
    }
    for (int i = tid; i < Sn * Sn; i += 128) at[i] = 0.f;
    __syncthreads();

    int h = tid >> 5;
    int qi = tid & 31;
    const float scale = 0.17677669529663687f;  // 1/sqrt(32)
    float sc[Sn];
    float mx = -1e30f;
#pragma unroll
    for (int j = 0; j < Sn; j++) {
        float dsum = 0.f;
#pragma unroll
        for (int hd = 0; hd < HDn; hd++)
            dsum += qs[(h * HDn + hd) * 33 + qi] * ks[j * Dn + h * HDn + hd];
        sc[j] = dsum * scale;
        mx = fmaxf(mx, sc[j]);
    }
    float se = 0.f;
#pragma unroll
    for (int j = 0; j < Sn; j++) { sc[j] = expf(sc[j] - mx); se += sc[j]; }
    float inv = 0.25f / se;
#pragma unroll
    for (int j = 0; j < Sn; j++) atomicAdd(&at[qi * Sn + j], sc[j] * inv);
    __syncthreads();
    for (int i = tid; i < Sn * Sn; i += 128) attn[(size_t)g * Sn * Sn + i] = at[i];
}

// ---------------- x_atten[g,n,d] = sum_s attn[g,s,n]*xh[g,s,n,d] -> half ----------------
__global__ void xatten_kernel(const __half* __restrict__ xh, const float* __restrict__ attn,
                              __half* __restrict__ xatth)
{
    int b = blockIdx.x;                 // g*Nn + n
    int g = b >> 5, n = b & 31;
    int d = threadIdx.x;                // 128
    __shared__ float coef[Sn];
    if (d < Sn) coef[d] = attn[(size_t)g * Sn * Sn + d * Sn + n];
    __syncthreads();
    float acc = 0.f;
#pragma unroll 8
    for (int s = 0; s < Sn; s++)
        acc += coef[s] * __half2float(xh[(size_t)((g * Sn + s) * Nn + n) * Dn + d]);
    xatth[(size_t)b * Dn + d] = __float2half_rn(acc);
}

// ---------------- combine: relu(BN1(c1)+h2) -> xh mirror + submean (no fp32 x output) ----------------
__global__ void combine_fused(const float* __restrict__ c1, const float* __restrict__ acc,
                              const float* __restrict__ gamma, const float* __restrict__ beta,
                              const float* __restrict__ h2,
                              float* __restrict__ sub, __half* __restrict__ subh,
                              __half* __restrict__ xh)
{
    int b = blockIdx.x;          // g*Sn + s
    int g = b >> 5;
    int d = threadIdx.x;         // 128
    float mu = acc[d] * (1.f / Tn);
    float var = acc[Dn + d] * (1.f / Tn) - mu * mu;
    const float sc = gamma[d] * rsqrtf(var + EPSn);
    const float sh = beta[d] - mu * sc;
    const float* c1p = c1 + (size_t)b * Nn * Dn;
    const float* h2p = h2 + (size_t)g * Nn * Dn;
    __half* xhp = xh ? (xh + (size_t)b * Nn * Dn) : nullptr;
    float s = 0.f;
#pragma unroll 4
    for (int n = 0; n < Nn; n++) {
        float v = fmaxf(sc * c1p[n * Dn + d] + sh + h2p[n * Dn + d], 0.f);
        if (xhp) xhp[n * Dn + d] = __float2half_rn(v);
        s += v;
    }
    float m = s * (1.f / Nn);
    sub[(size_t)b * Dn + d] = m;
    subh[(size_t)b * Dn + d] = __float2half_rn(m);
}

// ---------------- head: pool(sub) -> MLP -> logits, + heatmap copy ----------------
__global__ __launch_bounds__(256)
void head_kernel(const float* __restrict__ sub, const float* __restrict__ Wf1,
                 const float* __restrict__ bf1, const float* __restrict__ Wf2,
                 const float* __restrict__ bf2, const float* __restrict__ attn,
                 float* __restrict__ out)
{
    int g = blockIdx.x;
    int tid = threadIdx.x;  // 256
    __shared__ float hv[Dn];
    __shared__ float hid[2 * Dn];
    if (tid < Dn) {
        float s = 0.f;
#pragma unroll 8
        for (int i = 0; i < Sn; i++) s += sub[(size_t)(g * Sn + i) * Dn + tid];
        hv[tid] = s * (1.f / Sn);
    }
    __syncthreads();
    float a = bf1[tid];
#pragma unroll 8
    for (int k2 = 0; k2 < Dn; k2++) a += hv[k2] * Wf1[(size_t)k2 * 2 * Dn + tid];
    hid[tid] = fmaxf(a, 0.f);
    __syncthreads();
    if (tid < NTASK) {
        float o = bf2[tid];
        for (int k2 = 0; k2 < 2 * Dn; k2++) o += hid[k2] * Wf2[(size_t)k2 * NTASK + tid];
        out[(size_t)g * NTASK + tid] = o;
    }
    if (g == Gn - 1) {
        for (int i = tid; i < Sn * Sn; i += 256)
            out[Gn * NTASK + i] = attn[(size_t)(Gn - 1) * Sn * Sn + i];
    }
}

// ---------------- host orchestration ----------------
extern "C" void kernel_launch(void* const* d_in, const int* in_sizes, int n_in,
                              void* d_out, int out_size)
{
    const float* x_in = (const float*)d_in[0];
    const int*   ei   = (const int*)d_in[1];
    const int*   oei  = (const int*)d_in[2];
    const float* Wr1 = (const float*)d_in[3];
    const float* Wn1 = (const float*)d_in[4];
    const float* b1  = (const float*)d_in[5];
    const float* g1  = (const float*)d_in[6];
    const float* be1 = (const float*)d_in[7];
    const float* Wr2 = (const float*)d_in[8];
    const float* Wn2 = (const float*)d_in[9];
    const float* b2  = (const float*)d_in[10];
    const float* g2  = (const float*)d_in[11];
    const float* be2 = (const float*)d_in[12];
    const float* Wq  = (const float*)d_in[13];
    const float* bq  = (const float*)d_in[14];
    const float* Wk  = (const float*)d_in[15];
    const float* bk  = (const float*)d_in[16];
    const float* Wf1 = (const float*)d_in[17];
    const float* bf1 = (const float*)d_in[18];
    const float* Wf2 = (const float*)d_in[19];
    const float* bf2 = (const float*)d_in[20];
    float* out = (float*)d_out;

    float *pc1, *psub, *pq, *pk, *pattn, *pc2, *ph2, *pacc;
    __half *pxh, *pagg1h, *psubh, *pxatth, *pagg2h, *pwh;
    int *pdegs, *poffs, *pcurs, *psrcs, *pbsums;
    cudaGetSymbolAddress((void**)&pxh,    g_xh);
    cudaGetSymbolAddress((void**)&pagg1h, g_agg1h);
    cudaGetSymbolAddress((void**)&pc1,    g_c1);
    cudaGetSymbolAddress((void**)&psub,   g_sub);
    cudaGetSymbolAddress((void**)&psubh,  g_subh);
    cudaGetSymbolAddress((void**)&pq,     g_q);
    cudaGetSymbolAddress((void**)&pk,     g_k);
    cudaGetSymbolAddress((void**)&pattn,  g_attn);
    cudaGetSymbolAddress((void**)&pxatth, g_xatth);
    cudaGetSymbolAddress((void**)&pagg2h, g_agg2h);
    cudaGetSymbolAddress((void**)&pc2,    g_c2);
    cudaGetSymbolAddress((void**)&ph2,    g_h2);
    cudaGetSymbolAddress((void**)&pacc,   g_acc);
    cudaGetSymbolAddress((void**)&pwh,    g_wh);
    cudaGetSymbolAddress((void**)&pdegs,  g_degs);
    cudaGetSymbolAddress((void**)&poffs,  g_offs);
    cudaGetSymbolAddress((void**)&pcurs,  g_curs);
    cudaGetSymbolAddress((void**)&psrcs,  g_srcs_all);
    cudaGetSymbolAddress((void**)&pbsums, g_bsums);

    // ---- startup: weight convert, half mirror + deg zero, CSR build (parallel scan) ----
    wconv_kernel<<<dim3(Ln * Dn * Dn / 256, 6), 256>>>(Wr1, Wn1, Wr2, Wn2, Wq, Wk, pwh);
    x2half_kernel<<<(Tn * Dn / 2) / 256, 256>>>(x_in, pxh, pdegs);
    hist_both<<<(En + EOn) / 256, 256>>>(ei + En, oei + EOn, pdegs);
    scanA<<<NBLK_ALL, 1024>>>(pdegs, poffs, pbsums);
    scanB<<<1, 256>>>(pbsums);
    scanC<<<NBLK_ALL, 1024>>>(poffs, pcurs, pbsums);
    fill_both<<<(En + EOn) / 256, 256>>>(ei, oei, pcurs, psrcs);

    const int* poffBig = poffs;
    const int* poffSm  = poffs + Tn + 1;
    const int* psrcBig = psrcs;
    const int* psrcSm  = psrcs + En;
    const size_t WSZ = (size_t)Ln * Dn * Dn;

    for (int i = 0; i < Ln; i++) {
        const size_t wOff = (size_t)i * Dn * Dn;
        const size_t vOff = (size_t)i * Dn;
        const __half* Wr1h = pwh + 0 * WSZ + wOff;
        const __half* Wn1h = pwh + 1 * WSZ + wOff;
        const __half* Wr2h = pwh + 2 * WSZ + wOff;
        const __half* Wn2h = pwh + 3 * WSZ + wOff;
        const __half* Wqh  = pwh + 4 * WSZ + wOff;
        const __half* Wkh  = pwh + 5 * WSZ + wOff;

        // subgraph-level GraphConv (+ fused BN stats; gather zeroes the stat acc)
        gather_half<<<(Tn * 32) / 256, 256>>>(pxh, poffBig, psrcBig, pagg1h, Tn, pacc);
        conv_gemm_f16<<<Tn / 128, 256>>>(pxh, pagg1h, Wr1h, Wn1h, b1 + vOff, pc1, pacc,
                                         nullptr, nullptr, nullptr);

        // attention branch
        if (i == 0) submean_kernel<<<Gn * Sn, 128>>>(x_in, psub, psubh);
        conv_gemm_f16<<<dim3((Gn * Sn) / 128, 2), 256>>>(
            psubh, nullptr, Wqh, nullptr, bq + vOff, pq, nullptr,
            Wkh, bk + vOff, pk);
        attn_kernel<<<Gn, 128>>>(pq, pk, pattn);
        xatten_kernel<<<Gn * Nn, 128>>>(pxh, pattn, pxatth);

        // original-graph GraphConv (+ fused BN stats)
        gather_half<<<(TOn * 32) / 256, 256>>>(pxatth, poffSm, psrcSm, pagg2h, TOn, nullptr);
        conv_gemm_f16<<<TOn / 128, 256>>>(pxatth, pagg2h, Wr2h, Wn2h, b2 + vOff, pc2,
                                          pacc + 256, nullptr, nullptr, nullptr);
        bn_apply2<<<(TOn * Dn) / 256, 256>>>(pc2, pacc + 256, g2 + vOff, be2 + vOff, ph2);

        // relu(BN1(c1) + h2 broadcast) -> next-layer xh mirror + submean
        combine_fused<<<Gn * Sn, 128>>>(pc1, pacc, g1 + vOff, be1 + vOff, ph2,
                                        psub, psubh, (i < Ln - 1) ? pxh : nullptr);
    }

    head_kernel<<<Gn, 256>>>(psub, Wf1, bf1, Wf2, bf2, pattn, out);
}